// round 1
// baseline (speedup 1.0000x reference)
#include <cuda_runtime.h>
#include <math.h>

#define HDIM 256
#define WDIM 256
#define WF   129
#define BSZ  4
#define CSZ  128
#define NBLK 8
#define BLK  16

// scratch spectrum buffer, layout [b, c, wf, h] as float2 (~135 MB)
__device__ float2 g_buf[(size_t)BSZ * CSZ * WF * HDIM];

__device__ __forceinline__ float2 cmul(float2 a, float2 b) {
    return make_float2(a.x * b.x - a.y * b.y, a.x * b.y + a.y * b.x);
}

// Batched radix-4 Stockham FFT, N=256, nfft rows resident in smem.
// x0/y0: ping-pong buffers of nfft*256 float2. tw: 64-entry table exp(-2*pi*i*k/256).
// Result ends in x0 (4 stages = even number of swaps). All threads must participate.
__device__ __forceinline__ void fft256_r4(float2* x0, float2* y0, const float2* tw,
                                          int nfft, int tid, int nthr, bool inv) {
    float2* x = x0;
    float2* y = y0;
#pragma unroll
    for (int t = 0; t < 4; t++) {
        const int s = 1 << (2 * t);
        const int items = nfft * 64;
        const int m = 64 >> (2 * t);
        for (int it = tid; it < items; it += nthr) {
            const int f = it >> 6;
            const int idx = it & 63;
            const int p = idx >> (2 * t);
            const int q = idx & (s - 1);
            const float2* xr = x + f * 256;
            float2* yr = y + f * 256;
            float2 a = xr[q + s * p];
            float2 b = xr[q + s * (p + m)];
            float2 c = xr[q + s * (p + 2 * m)];
            float2 d = xr[q + s * (p + 3 * m)];
            float2 apc = make_float2(a.x + c.x, a.y + c.y);
            float2 amc = make_float2(a.x - c.x, a.y - c.y);
            float2 bpd = make_float2(b.x + d.x, b.y + d.y);
            float2 bmd = make_float2(b.x - d.x, b.y - d.y);
            float2 ib  = make_float2(-bmd.y, bmd.x);   // i*(b-d)
            float2 r0 = make_float2(apc.x + bpd.x, apc.y + bpd.y);
            float2 r2 = make_float2(apc.x - bpd.x, apc.y - bpd.y);
            float2 r1, r3;
            if (!inv) {
                r1 = make_float2(amc.x - ib.x, amc.y - ib.y);
                r3 = make_float2(amc.x + ib.x, amc.y + ib.y);
            } else {
                r1 = make_float2(amc.x + ib.x, amc.y + ib.y);
                r3 = make_float2(amc.x - ib.x, amc.y - ib.y);
            }
            float2 w1 = tw[p << (2 * t)];
            if (inv) w1.y = -w1.y;
            float2 w2 = cmul(w1, w1);
            float2 w3 = cmul(w2, w1);
            yr[q + s * (4 * p + 0)] = r0;
            yr[q + s * (4 * p + 1)] = cmul(r1, w1);
            yr[q + s * (4 * p + 2)] = cmul(r2, w2);
            yr[q + s * (4 * p + 3)] = cmul(r3, w3);
        }
        __syncthreads();
        float2* tmp = x; x = y; y = tmp;
    }
}

__device__ __forceinline__ void init_tw(float2* tw, int tid) {
    if (tid < 64) {
        float s, c;
        sincosf((float)tid * (-6.283185307179586f / 256.f), &s, &c);
        tw[tid] = make_float2(c, s);
    }
}

// K1: per (b,c) image, 16 rows per CTA: rfft-256 along W (via full complex FFT, imag=0),
// scale by 1/256 (ortho forward), write transposed [b,c,wf,h].
__global__ void k_rowfft(const float* __restrict__ x) {
    extern __shared__ float2 sm[];
    float2* A  = sm;            // 4096
    float2* Bp = sm + 4096;     // 4096
    float2* tw = sm + 8192;     // 64
    const int tid = threadIdx.x;
    const int bc = blockIdx.x >> 4;
    const int h0 = (blockIdx.x & 15) << 4;

    init_tw(tw, tid);
    const float* src = x + ((size_t)bc * HDIM + h0) * WDIM;
    for (int e = tid; e < 16 * 256; e += 256)
        A[e] = make_float2(src[e], 0.f);
    __syncthreads();

    fft256_r4(A, Bp, tw, 16, tid, 256, false);

    float2* dst = g_buf + (size_t)bc * WF * HDIM;
    for (int e = tid; e < 129 * 16; e += 256) {
        const int wf = e >> 4, r = e & 15;
        float2 v = A[r * 256 + wf];
        dst[(size_t)wf * HDIM + h0 + r] =
            make_float2(v.x * (1.f / 256.f), v.y * (1.f / 256.f));
    }
}

// K2: per (b, block k, wf): column FFT-256 over h for 16 channels, block-MLP per h,
// inverse column FFT, in-place on g_buf.
__global__ void k_colfft_mlp(const float* __restrict__ w1g, const float* __restrict__ b1g,
                             const float* __restrict__ w2g, const float* __restrict__ b2g) {
    extern __shared__ float2 sm[];
    float2* A  = sm;
    float2* Bp = sm + 4096;
    float2* tw = sm + 8192;
    float* W = (float*)(sm + 8192 + 64);
    float* w1r = W;          // 256
    float* w1i = W + 256;
    float* w2r = W + 512;
    float* w2i = W + 768;
    float* bb  = W + 1024;   // b1r[16] b1i[16] b2r[16] b2i[16]

    const int tid = threadIdx.x;
    const int wf = blockIdx.x % 129;
    const int bk = blockIdx.x / 129;
    const int k = bk & 7;
    const int b = bk >> 3;

    init_tw(tw, tid);
    // weights: w1/w2 are [2][8][16][16], b1/b2 are [2][8][16]
    w1r[tid] = w1g[k * 256 + tid];
    w1i[tid] = w1g[(8 + k) * 256 + tid];
    w2r[tid] = w2g[k * 256 + tid];
    w2i[tid] = w2g[(8 + k) * 256 + tid];
    if (tid < 16) {
        bb[tid]      = b1g[k * 16 + tid];
        bb[16 + tid] = b1g[128 + k * 16 + tid];
        bb[32 + tid] = b2g[k * 16 + tid];
        bb[48 + tid] = b2g[128 + k * 16 + tid];
    }

    float2* gsrc = g_buf + ((size_t)(b * CSZ + k * 16) * WF + wf) * HDIM;
    for (int e = tid; e < 4096; e += 256) {
        const int i = e >> 8, h = e & 255;
        A[e] = gsrc[(size_t)i * WF * HDIM + h];
    }
    __syncthreads();

    fft256_r4(A, Bp, tw, 16, tid, 256, false);

    // MLP: one thread per h column
    {
        const int h = tid;
        float xr[16], xi[16];
#pragma unroll
        for (int i = 0; i < 16; i++) {
            float2 v = A[i * 256 + h];
            xr[i] = v.x; xi[i] = v.y;
        }
        float o1r[16], o1i[16];
#pragma unroll
        for (int o = 0; o < 16; o++) {
            float ar = bb[o], ai = bb[16 + o];
#pragma unroll
            for (int i = 0; i < 16; i++) {
                const float wr = w1r[i * 16 + o], wi = w1i[i * 16 + o];
                ar += xr[i] * wr - xi[i] * wi;
                ai += xi[i] * wr + xr[i] * wi;
            }
            o1r[o] = fmaxf(ar, 0.f);
            o1i[o] = fmaxf(ai, 0.f);
        }
#pragma unroll
        for (int o = 0; o < 16; o++) {
            float ar = bb[32 + o], ai = bb[48 + o];
#pragma unroll
            for (int i = 0; i < 16; i++) {
                const float wr = w2r[i * 16 + o], wi = w2i[i * 16 + o];
                ar += o1r[i] * wr - o1i[i] * wi;
                ai += o1i[i] * wr + o1r[i] * wi;
            }
            // softshrink(lambda=0.01)
            const float sr = copysignf(fmaxf(fabsf(ar) - 0.01f, 0.f), ar);
            const float si = copysignf(fmaxf(fabsf(ai) - 0.01f, 0.f), ai);
            float2 v;
            v.x = sr * xr[o] - si * xi[o];
            v.y = sr * xi[o] + si * xr[o];
            A[o * 256 + h] = v;
        }
    }
    __syncthreads();

    fft256_r4(A, Bp, tw, 16, tid, 256, true);

    for (int e = tid; e < 4096; e += 256) {
        const int i = e >> 8, h = e & 255;
        gsrc[(size_t)i * WF * HDIM + h] = A[e];
    }
}

// K3: per (b,c), 16 rows per CTA: gather [wf,h] tile, Hermitian-extend to 256 bins,
// inverse FFT along W, scale 1/256 (ortho inverse), add residual x, write out.
__global__ void k_rowifft(const float* __restrict__ x, float* __restrict__ out) {
    extern __shared__ float2 sm[];
    float2* A  = sm;
    float2* Bp = sm + 4096;
    float2* tw = sm + 8192;
    const int tid = threadIdx.x;
    const int bc = blockIdx.x >> 4;
    const int h0 = (blockIdx.x & 15) << 4;

    init_tw(tw, tid);
    const float2* gsrc = g_buf + (size_t)bc * WF * HDIM;
    for (int e = tid; e < 129 * 16; e += 256) {
        const int wf = e >> 4, r = e & 15;
        A[r * 256 + wf] = gsrc[(size_t)wf * HDIM + h0 + r];
    }
    __syncthreads();
    // Hermitian fill: bins 129..255 = conj(bins 127..1) (disjoint from read range)
    for (int e = tid; e < 127 * 16; e += 256) {
        const int w = 129 + (e >> 4);
        const int r = e & 15;
        float2 v = A[r * 256 + (256 - w)];
        A[r * 256 + w] = make_float2(v.x, -v.y);
    }
    __syncthreads();

    fft256_r4(A, Bp, tw, 16, tid, 256, true);

    const float* bias = x + ((size_t)bc * HDIM + h0) * WDIM;
    float* dst = out + ((size_t)bc * HDIM + h0) * WDIM;
    for (int e = tid; e < 4096; e += 256)
        dst[e] = A[e].x * (1.f / 256.f) + bias[e];
}

extern "C" void kernel_launch(void* const* d_in, const int* in_sizes, int n_in,
                              void* d_out, int out_size) {
    const float* x  = (const float*)d_in[0];
    const float* w1 = (const float*)d_in[1];
    const float* b1 = (const float*)d_in[2];
    const float* w2 = (const float*)d_in[3];
    const float* b2 = (const float*)d_in[4];
    float* out = (float*)d_out;

    const int SMEM_FFT = (4096 + 4096 + 64) * (int)sizeof(float2);          // 66048
    const int SMEM_MLP = SMEM_FFT + 1088 * (int)sizeof(float);              // 70400

    cudaFuncSetAttribute(k_rowfft,     cudaFuncAttributeMaxDynamicSharedMemorySize, SMEM_FFT);
    cudaFuncSetAttribute(k_colfft_mlp, cudaFuncAttributeMaxDynamicSharedMemorySize, SMEM_MLP);
    cudaFuncSetAttribute(k_rowifft,    cudaFuncAttributeMaxDynamicSharedMemorySize, SMEM_FFT);

    k_rowfft<<<BSZ * CSZ * (HDIM / 16), 256, SMEM_FFT>>>(x);
    k_colfft_mlp<<<BSZ * NBLK * WF, 256, SMEM_MLP>>>(w1, b1, w2, b2);
    k_rowifft<<<BSZ * CSZ * (HDIM / 16), 256, SMEM_FFT>>>(x, out);
}

// round 2
// speedup vs baseline: 2.9910x; 2.9910x over previous
#include <cuda_runtime.h>
#include <math.h>

#define HDIM 256
#define WDIM 256
#define WF   129
#define BSZ  4
#define CSZ  128
#define NBLK 8

// scratch spectrum buffer, layout [b, c, wf, h] as float2 (~135 MB)
__device__ float2 g_buf[(size_t)BSZ * CSZ * WF * HDIM];

__device__ __forceinline__ float2 cadd(float2 a, float2 b){ return make_float2(a.x+b.x, a.y+b.y); }
__device__ __forceinline__ float2 csub(float2 a, float2 b){ return make_float2(a.x-b.x, a.y-b.y); }
__device__ __forceinline__ float2 cmul(float2 a, float2 b){
    return make_float2(a.x*b.x - a.y*b.y, a.x*b.y + a.y*b.x);
}
__device__ __forceinline__ float2 cmulc(float2 a, float2 b){  // a * conj(b)
    return make_float2(a.x*b.x + a.y*b.y, a.y*b.x - a.x*b.y);
}

// multiply by (-i) forward, (+i) inverse
template<bool INV>
__device__ __forceinline__ float2 mul_i(float2 a){
    return INV ? make_float2(-a.y, a.x) : make_float2(a.y, -a.x);
}

template<bool INV>
__device__ __forceinline__ void bf4(float2& x0, float2& x1, float2& x2, float2& x3){
    float2 t0 = cadd(x0, x2), t1 = csub(x0, x2);
    float2 t2 = cadd(x1, x3), t3 = csub(x1, x3);
    float2 j3 = mul_i<INV>(t3);
    x0 = cadd(t0, t2);
    x2 = csub(t0, t2);
    x1 = cadd(t1, j3);
    x3 = csub(t1, j3);
}

// In-register 16-point DFT (radix-4 x radix-4). Input v[n] natural order.
// Output: bin k = c + 4d lands in slot 4c + d  (slot(k) = ((k&3)<<2)|(k>>2)).
template<bool INV>
__device__ __forceinline__ void dft16(float2 v[16]){
    const float S = INV ? 1.f : -1.f;
    const float2 W1 = make_float2( 0.92387953251128674f, S*0.38268343236508978f);
    const float2 W2 = make_float2( 0.70710678118654752f, S*0.70710678118654752f);
    const float2 W3 = make_float2( 0.38268343236508978f, S*0.92387953251128674f);
    const float2 W6 = make_float2(-0.70710678118654752f, S*0.70710678118654752f);
    const float2 W9 = make_float2(-0.92387953251128674f, -S*0.38268343236508978f);

    bf4<INV>(v[0], v[4], v[8],  v[12]);
    bf4<INV>(v[1], v[5], v[9],  v[13]);
    bf4<INV>(v[2], v[6], v[10], v[14]);
    bf4<INV>(v[3], v[7], v[11], v[15]);
    // v[b+4c] = s_b[c];  twiddle W16^{b*c}
    v[5]  = cmul(v[5],  W1);
    v[9]  = cmul(v[9],  W2);
    v[13] = cmul(v[13], W3);
    v[6]  = cmul(v[6],  W2);
    v[10] = mul_i<INV>(v[10]);           // W16^4 = -/+ i
    v[14] = cmul(v[14], W6);
    v[7]  = cmul(v[7],  W3);
    v[11] = cmul(v[11], W6);
    v[15] = cmul(v[15], W9);
    bf4<INV>(v[0],  v[1],  v[2],  v[3]);
    bf4<INV>(v[4],  v[5],  v[6],  v[7]);
    bf4<INV>(v[8],  v[9],  v[10], v[11]);
    bf4<INV>(v[12], v[13], v[14], v[15]);
}

#define SLOT(k) ((((k) & 3) << 2) | ((k) >> 2))

__device__ __forceinline__ void build_tw(float2* tw, int tid){
    float s, c;
    sincosf((float)tid * (-6.283185307179586f / 256.f), &s, &c);
    tw[tid] = make_float2(c, s);
}

// ---------------------------------------------------------------------------
// K1: row rfft. CTA = 32 rows of one (b,c) image, packed 2 real rows / complex
// FFT (16 FFTs, 16 threads each). Output transposed [b,c,wf,h], scaled 1/256.
// ---------------------------------------------------------------------------
__global__ void __launch_bounds__(256) k_rowfft(const float* __restrict__ x){
    extern __shared__ char smraw[];
    float2* sbuf = (float2*)smraw;                 // 4352 float2 (T:272/fft, S:257/fft)
    float2* tw   = (float2*)(smraw + 34816);       // 256 float2

    const int tid = threadIdx.x;
    const int f = tid >> 4, t = tid & 15;
    const int bc = blockIdx.x >> 3;
    const int h0 = (blockIdx.x & 7) << 5;

    build_tw(tw, tid);

    const float* r0 = x + ((size_t)bc * HDIM + h0 + 2 * f) * WDIM;
    float2 v[16];
#pragma unroll
    for (int n1 = 0; n1 < 16; n1++)
        v[n1] = make_float2(r0[16 * n1 + t], r0[WDIM + 16 * n1 + t]);
    dft16<false>(v);
    __syncthreads();                               // tw ready

#pragma unroll
    for (int k1 = 0; k1 < 16; k1++){
        float2 bv = v[SLOT(k1)];
        if (k1) bv = cmul(bv, tw[t * k1]);
        sbuf[f * 272 + k1 * 17 + t] = bv;
    }
    __syncthreads();
#pragma unroll
    for (int n2 = 0; n2 < 16; n2++)
        v[n2] = sbuf[f * 272 + t * 17 + n2];
    __syncthreads();                               // T reads done before S writes
    dft16<false>(v);
#pragma unroll
    for (int k2 = 0; k2 < 16; k2++)
        sbuf[f * 257 + t + 16 * k2] = v[SLOT(k2)];
    __syncthreads();

    float2* dst = g_buf + (size_t)bc * WF * HDIM;
    for (int e = tid; e < WF * 32; e += 256){
        const int wf = e >> 5, r = e & 31, fp = r >> 1;
        float2 Z1 = sbuf[fp * 257 + wf];
        float2 Z2 = sbuf[fp * 257 + ((256 - wf) & 255)];
        float2 val = (r & 1)
            ? make_float2((Z1.y + Z2.y) * 0.5f, (Z2.x - Z1.x) * 0.5f)
            : make_float2((Z1.x + Z2.x) * 0.5f, (Z1.y - Z2.y) * 0.5f);
        dst[(size_t)wf * HDIM + h0 + r] =
            make_float2(val.x * (1.f / 256.f), val.y * (1.f / 256.f));
    }
}

// ---------------------------------------------------------------------------
// K2: column FFT over h (16 channels of one block), per-bin block MLP,
// inverse column FFT. In-place on g_buf, unnormalized round trip.
// ---------------------------------------------------------------------------
__global__ void __launch_bounds__(256) k_colfft_mlp(
        const float* __restrict__ w1g, const float* __restrict__ b1g,
        const float* __restrict__ w2g, const float* __restrict__ b2g){
    extern __shared__ char smraw[];
    float2* T   = (float2*)smraw;                  // 4352 f2
    float2* A   = (float2*)(smraw + 34816);        // 4112 f2
    float2* tw  = (float2*)(smraw + 67712);        // 256 f2
    float2* w1c = (float2*)(smraw + 69760);        // 256 f2
    float2* w2c = (float2*)(smraw + 71808);        // 256 f2
    float2* b1c = (float2*)(smraw + 73856);        // 16 f2
    float2* b2c = (float2*)(smraw + 73984);        // 16 f2

    const int tid = threadIdx.x;
    const int f = tid >> 4, t = tid & 15;
    const int wf = blockIdx.x % WF;
    const int bk = blockIdx.x / WF;
    const int k = bk & 7, b = bk >> 3;

    build_tw(tw, tid);
    w1c[tid] = make_float2(w1g[k * 256 + tid], w1g[2048 + k * 256 + tid]);
    w2c[tid] = make_float2(w2g[k * 256 + tid], w2g[2048 + k * 256 + tid]);
    if (tid < 16){
        b1c[tid] = make_float2(b1g[k * 16 + tid], b1g[128 + k * 16 + tid]);
        b2c[tid] = make_float2(b2g[k * 16 + tid], b2g[128 + k * 16 + tid]);
    }

    float2* chp = g_buf + ((size_t)(b * CSZ + k * 16 + f) * WF + wf) * HDIM;

    float2 v[16];
#pragma unroll
    for (int n1 = 0; n1 < 16; n1++) v[n1] = chp[16 * n1 + t];
    dft16<false>(v);
    __syncthreads();                               // tw + weights ready
#pragma unroll
    for (int k1 = 0; k1 < 16; k1++){
        float2 bv = v[SLOT(k1)];
        if (k1) bv = cmul(bv, tw[t * k1]);
        T[f * 272 + k1 * 17 + t] = bv;
    }
    __syncthreads();
#pragma unroll
    for (int n2 = 0; n2 < 16; n2++) v[n2] = T[f * 272 + t * 17 + n2];
    dft16<false>(v);
#pragma unroll
    for (int k2 = 0; k2 < 16; k2++)
        A[f * 257 + t + 16 * k2] = v[SLOT(k2)];
    __syncthreads();

    // ---- MLP: one thread per h-bin, mixing the 16 channels ----
    {
        float xr[16], xi[16];
#pragma unroll
        for (int i = 0; i < 16; i++){
            float2 q = A[i * 257 + tid];
            xr[i] = q.x; xi[i] = q.y;
        }
        float o1r[16], o1i[16];
#pragma unroll
        for (int o = 0; o < 16; o++){
            float ar = b1c[o].x, ai = b1c[o].y;
#pragma unroll
            for (int i = 0; i < 16; i++){
                float2 w = w1c[i * 16 + o];
                ar = fmaf(xr[i], w.x, ar); ar = fmaf(-xi[i], w.y, ar);
                ai = fmaf(xi[i], w.x, ai); ai = fmaf( xr[i], w.y, ai);
            }
            o1r[o] = fmaxf(ar, 0.f);
            o1i[o] = fmaxf(ai, 0.f);
        }
#pragma unroll
        for (int o = 0; o < 16; o++){
            float ar = b2c[o].x, ai = b2c[o].y;
#pragma unroll
            for (int i = 0; i < 16; i++){
                float2 w = w2c[i * 16 + o];
                ar = fmaf(o1r[i], w.x, ar); ar = fmaf(-o1i[i], w.y, ar);
                ai = fmaf(o1i[i], w.x, ai); ai = fmaf( o1r[i], w.y, ai);
            }
            const float sr = copysignf(fmaxf(fabsf(ar) - 0.01f, 0.f), ar);
            const float si = copysignf(fmaxf(fabsf(ai) - 0.01f, 0.f), ai);
            A[o * 257 + tid] = make_float2(sr * xr[o] - si * xi[o],
                                           sr * xi[o] + si * xr[o]);
        }
    }
    __syncthreads();

    // ---- inverse column FFT (bin-strided in, coalesced time-domain out) ----
#pragma unroll
    for (int k2 = 0; k2 < 16; k2++) v[k2] = A[f * 257 + t + 16 * k2];
    dft16<true>(v);
#pragma unroll
    for (int m2 = 0; m2 < 16; m2++){
        float2 q = v[SLOT(m2)];
        if (m2) q = cmulc(q, tw[m2 * t]);
        T[f * 272 + m2 * 17 + t] = q;
    }
    __syncthreads();
#pragma unroll
    for (int n = 0; n < 16; n++) v[n] = T[f * 272 + t * 17 + n];
    dft16<true>(v);
#pragma unroll
    for (int m1 = 0; m1 < 16; m1++)
        chp[16 * m1 + t] = v[SLOT(m1)];
}

// ---------------------------------------------------------------------------
// K3: row irfft. CTA = 32 rows of one (b,c) image, 2 rows packed per inverse
// complex FFT. Hermitian extension + edge-bin imag zeroing == irfft semantics.
// Scale 1/256, add residual.
// ---------------------------------------------------------------------------
__global__ void __launch_bounds__(256) k_rowifft(const float* __restrict__ x,
                                                 float* __restrict__ out){
    extern __shared__ char smraw[];
    float2* sbuf = (float2*)smraw;                 // 4352 f2
    float2* tw   = (float2*)(smraw + 34816);       // 256 f2

    const int tid = threadIdx.x;
    const int f = tid >> 4, t = tid & 15;
    const int bc = blockIdx.x >> 3;
    const int h0 = (blockIdx.x & 7) << 5;

    build_tw(tw, tid);

    const float2* gsrc = g_buf + (size_t)bc * WF * HDIM;
    // Build packed full spectrum Z[f][0..255], Z = X0 + i*X1
    for (int e = tid; e < WF * 16; e += 256){
        const int wf = e >> 4, fp = e & 15;
        float4 q = *(const float4*)(gsrc + (size_t)wf * HDIM + h0 + 2 * fp);
        float ay = q.y, by = q.w;
        if (wf == 0 || wf == 128){ ay = 0.f; by = 0.f; }   // irfft ignores edge imag
        sbuf[fp * 257 + wf] = make_float2(q.x - by, ay + q.z);
        if (wf >= 1 && wf <= 127)
            sbuf[fp * 257 + 256 - wf] = make_float2(q.x + by, q.z - ay);
    }
    __syncthreads();

    float2 v[16];
#pragma unroll
    for (int k2 = 0; k2 < 16; k2++) v[k2] = sbuf[f * 257 + t + 16 * k2];
    __syncthreads();                               // S reads done before T writes
    dft16<true>(v);
#pragma unroll
    for (int m2 = 0; m2 < 16; m2++){
        float2 q = v[SLOT(m2)];
        if (m2) q = cmulc(q, tw[m2 * t]);
        sbuf[f * 272 + m2 * 17 + t] = q;
    }
    __syncthreads();
#pragma unroll
    for (int n = 0; n < 16; n++) v[n] = sbuf[f * 272 + t * 17 + n];
    dft16<true>(v);

    const float* bias0 = x   + ((size_t)bc * HDIM + h0 + 2 * f) * WDIM;
    float*       o0    = out + ((size_t)bc * HDIM + h0 + 2 * f) * WDIM;
#pragma unroll
    for (int m1 = 0; m1 < 16; m1++){
        float2 z = v[SLOT(m1)];
        const int w_ = 16 * m1 + t;
        o0[w_]        = z.x * (1.f / 256.f) + bias0[w_];
        o0[WDIM + w_] = z.y * (1.f / 256.f) + bias0[WDIM + w_];
    }
}

extern "C" void kernel_launch(void* const* d_in, const int* in_sizes, int n_in,
                              void* d_out, int out_size) {
    const float* x  = (const float*)d_in[0];
    const float* w1 = (const float*)d_in[1];
    const float* b1 = (const float*)d_in[2];
    const float* w2 = (const float*)d_in[3];
    const float* b2 = (const float*)d_in[4];
    float* out = (float*)d_out;

    const int SMEM_ROW = 34816 + 2048;             // 36864
    const int SMEM_COL = 74112;

    cudaFuncSetAttribute(k_rowfft,     cudaFuncAttributeMaxDynamicSharedMemorySize, SMEM_ROW);
    cudaFuncSetAttribute(k_colfft_mlp, cudaFuncAttributeMaxDynamicSharedMemorySize, SMEM_COL);
    cudaFuncSetAttribute(k_rowifft,    cudaFuncAttributeMaxDynamicSharedMemorySize, SMEM_ROW);

    k_rowfft<<<BSZ * CSZ * (HDIM / 32), 256, SMEM_ROW>>>(x);
    k_colfft_mlp<<<BSZ * NBLK * WF, 256, SMEM_COL>>>(w1, b1, w2, b2);
    k_rowifft<<<BSZ * CSZ * (HDIM / 32), 256, SMEM_ROW>>>(x, out);
}